// round 3
// baseline (speedup 1.0000x reference)
#include <cuda_runtime.h>

#define N_NODES 20000
#define N_EDGES 320000
#define E_TOT   (N_EDGES + N_NODES)
#define N_GRAPHS 64

// ---------------- scratch (device globals; no allocation allowed) ----------
__device__ float g_als1[N_NODES * 8];
__device__ float g_ald1[N_NODES * 8];
__device__ float g_o1[N_NODES * 64];
__device__ float g_t2[N_NODES * 64];
__device__ float g_als2[N_NODES];
__device__ float g_ald2[N_NODES];
__device__ float g_va[64];
__device__ float g_vd[64];
__device__ float g_Ps[24];
__device__ float g_Pd[24];
__device__ int   g_deg[N_NODES];
__device__ int   g_fill[N_NODES];        // seeded to rowstart by k_scan
__device__ int   g_rowstart[N_NODES + 1];
__device__ int   g_csr[E_TOT];
__device__ float g_pool[N_GRAPHS * 512];
__device__ int   g_cnt[N_GRAPHS];

// ============ K1: init pool/deg + P + va + per-graph counts (fused) =========
// blocks 0..127   : zero g_pool (32768) and g_deg (20000)
// block  128      : t<24 -> P;  t in [32,96) -> cnt via binary search (batch sorted)
// blocks 129..136 : va/vd (64 warps)
__global__ void k_setup(const float* __restrict__ W1, const float* __restrict__ as1,
                        const float* __restrict__ ad1, const float* __restrict__ W2,
                        const float* __restrict__ as2, const float* __restrict__ ad2,
                        const int* __restrict__ batch) {
    int b = blockIdx.x, t = threadIdx.x;
    if (b < 128) {
        int idx = b * 256 + t;
        g_pool[idx] = 0.f;                       // 128*256 == 32768 exactly
        if (idx < N_NODES) g_deg[idx] = 0;
    } else if (b == 128) {
        if (t < 24) {
            int h = t / 3, d = t % 3;
            float ps = 0.f, pd = 0.f;
            for (int c = 0; c < 8; c++) {
                float w = W1[d * 64 + h * 8 + c];
                ps += w * as1[h * 8 + c];
                pd += w * ad1[h * 8 + c];
            }
            g_Ps[t] = ps;
            g_Pd[t] = pd;
        } else if (t >= 32 && t < 96) {
            int g = t - 32;
            int lo = 0, hi = N_NODES;
            while (lo < hi) { int m = (lo + hi) >> 1; if (batch[m] < g) lo = m + 1; else hi = m; }
            int s = lo;
            lo = 0; hi = N_NODES;
            int g1 = g + 1;
            while (lo < hi) { int m = (lo + hi) >> 1; if (batch[m] < g1) lo = m + 1; else hi = m; }
            g_cnt[g] = lo - s;
        }
    } else {
        int warp = (b - 129) * 8 + (t >> 5);     // 0..63
        int lane = t & 31;
        float s = 0.f, d = 0.f;
        for (int c = lane; c < 512; c += 32) {
            float w = W2[warp * 512 + c];
            s += w * as2[c];
            d += w * ad2[c];
        }
        for (int off = 16; off; off >>= 1) {
            s += __shfl_down_sync(0xffffffffu, s, off);
            d += __shfl_down_sync(0xffffffffu, d, off);
        }
        if (lane == 0) { g_va[warp] = s; g_vd[warp] = d; }
    }
}

// ---------------- CSR build (by dst), incl. self loops -----------------------
__global__ void k_hist(const int* __restrict__ ei) {
    int e = blockIdx.x * blockDim.x + threadIdx.x;
    if (e >= E_TOT) return;
    int dst = (e < N_EDGES) ? ei[N_EDGES + e] : (e - N_EDGES);
    atomicAdd(&g_deg[dst], 1);
}

__global__ void k_scan() {  // 1 block, 1024 threads; also seeds g_fill = rowstart
    __shared__ int part[1024];
    int tid = threadIdx.x;
    const int CH = 20;  // 1024*20 >= 20000
    int base = tid * CH;
    int s = 0;
    for (int i = 0; i < CH; i++) {
        int idx = base + i;
        if (idx < N_NODES) s += g_deg[idx];
    }
    part[tid] = s;
    __syncthreads();
    for (int off = 1; off < 1024; off <<= 1) {
        int v = (tid >= off) ? part[tid - off] : 0;
        __syncthreads();
        part[tid] += v;
        __syncthreads();
    }
    int run = (tid == 0) ? 0 : part[tid - 1];
    for (int i = 0; i < CH; i++) {
        int idx = base + i;
        if (idx < N_NODES) {
            g_rowstart[idx] = run;
            g_fill[idx] = run;
            run += g_deg[idx];
        }
    }
    if (tid == 1023) g_rowstart[N_NODES] = part[1023];
}

// ============ K4: scatter (blocks 0..1328) + al1 (blocks 1329..1953) =========
__global__ void k_scatter_al1(const int* __restrict__ ei, const float* __restrict__ x) {
    int b = blockIdx.x, t = threadIdx.x;
    if (b < 1329) {
        int e = b * 256 + t;
        if (e >= E_TOT) return;
        int src, dst;
        if (e < N_EDGES) { src = ei[e]; dst = ei[N_EDGES + e]; }
        else             { src = e - N_EDGES; dst = src; }
        int pos = atomicAdd(&g_fill[dst], 1);
        g_csr[pos] = src;
    } else {
        int idx = (b - 1329) * 256 + t;          // 625*256 == 160000 exactly
        int n = idx >> 3, h = idx & 7;
        float x0 = x[n * 3], x1 = x[n * 3 + 1], x2 = x[n * 3 + 2];
        g_als1[idx] = x0 * g_Ps[h * 3] + x1 * g_Ps[h * 3 + 1] + x2 * g_Ps[h * 3 + 2];
        g_ald1[idx] = x0 * g_Pd[h * 3] + x1 * g_Pd[h * 3 + 1] + x2 * g_Pd[h * 3 + 2];
    }
}

// ---------------- layer-1 aggregate + o1 + fused al2 logits ------------------
__global__ void k_agg1(const float* __restrict__ x, const float* __restrict__ W1,
                       const float* __restrict__ b1) {
    int gidx = blockIdx.x * 256 + threadIdx.x;  // exactly N_NODES*8 threads
    int n = gidx >> 3, h = gidx & 7;
    int s0 = g_rowstart[n], s1 = g_rowstart[n + 1];
    float ald = g_ald1[gidx];
    float wsum = 0.f, xa0 = 0.f, xa1 = 0.f, xa2 = 0.f;
    for (int i = s0; i < s1; i++) {
        int src = g_csr[i];
        float e = g_als1[src * 8 + h] + ald;
        e = (e > 0.f) ? e : 0.2f * e;
        float w = __expf(e);
        wsum += w;
        xa0 += w * x[src * 3 + 0];
        xa1 += w * x[src * 3 + 1];
        xa2 += w * x[src * 3 + 2];
    }
    float inv = 1.f / wsum;
    xa0 *= inv; xa1 *= inv; xa2 *= inv;
    float ps2 = 0.f, pd2 = 0.f;
#pragma unroll
    for (int c = 0; c < 8; c++) {
        int col = h * 8 + c;
        float o = xa0 * W1[col] + xa1 * W1[64 + col] + xa2 * W1[128 + col] + b1[col];
        o = (o > 0.f) ? o : (__expf(o) - 1.f);  // elu
        g_o1[n * 64 + col] = o;
        ps2 += o * g_va[col];
        pd2 += o * g_vd[col];
    }
    for (int off = 4; off; off >>= 1) {
        ps2 += __shfl_down_sync(0xffffffffu, ps2, off);
        pd2 += __shfl_down_sync(0xffffffffu, pd2, off);
    }
    if (h == 0) { g_als2[n] = ps2; g_ald2[n] = pd2; }
}

// ---------------- layer-2 aggregate in o1-space (64 wide) --------------------
__global__ void k_agg2() {
    int n = blockIdx.x;
    int t = threadIdx.x;  // 64
    int s0 = g_rowstart[n], s1 = g_rowstart[n + 1];
    float ald = g_ald2[n];
    float wsum = 0.f, acc = 0.f;
    for (int i = s0; i < s1; i++) {
        int src = g_csr[i];
        float e = g_als2[src] + ald;
        e = (e > 0.f) ? e : 0.2f * e;
        float w = __expf(e);
        wsum += w;
        acc += w * g_o1[src * 64 + t];
    }
    g_t2[n * 64 + t] = acc / wsum;
}

// ============ gemm2 v2: persistent, W2 in regs, f32x2 packed FFMA ============
// grid = 148 blocks x 512 threads; thread owns W2 column c (64 floats in regs).
// Tiles of 8 nodes stream through 2KB smem; 4 fma.rn.f32x2 per k.
__global__ void __launch_bounds__(512, 1)
k_gemm2(const float* __restrict__ W2, const float* __restrict__ b2,
        const int* __restrict__ batch) {
    __shared__ __align__(16) float shT[64 * 8];  // [k][node]
    int c = threadIdx.x;
    float w[64];
#pragma unroll
    for (int k = 0; k < 64; k++) w[k] = W2[k * 512 + c];
    float b2c = b2[c];
    const int NT = N_NODES / 8;  // 2500
    for (int tile = blockIdx.x; tile < NT; tile += gridDim.x) {
        int n0 = tile * 8;
        {
            int node = c >> 6, k = c & 63;
            shT[k * 8 + node] = g_t2[(n0 + node) * 64 + k];
        }
        __syncthreads();
        unsigned long long acc0 = 0ull, acc1 = 0ull, acc2 = 0ull, acc3 = 0ull;
#pragma unroll
        for (int k = 0; k < 64; k++) {
            unsigned long long w2;
            asm("mov.b64 %0, {%1, %1};" : "=l"(w2) : "f"(w[k]));
            const ulonglong2* p = reinterpret_cast<const ulonglong2*>(&shT[k * 8]);
            ulonglong2 q0 = p[0];
            ulonglong2 q1 = p[1];
            asm("fma.rn.f32x2 %0, %1, %2, %0;" : "+l"(acc0) : "l"(q0.x), "l"(w2));
            asm("fma.rn.f32x2 %0, %1, %2, %0;" : "+l"(acc1) : "l"(q0.y), "l"(w2));
            asm("fma.rn.f32x2 %0, %1, %2, %0;" : "+l"(acc2) : "l"(q1.x), "l"(w2));
            asm("fma.rn.f32x2 %0, %1, %2, %0;" : "+l"(acc3) : "l"(q1.y), "l"(w2));
        }
        __syncthreads();
        float vals[8];
        asm("mov.b64 {%0, %1}, %2;" : "=f"(vals[0]), "=f"(vals[1]) : "l"(acc0));
        asm("mov.b64 {%0, %1}, %2;" : "=f"(vals[2]), "=f"(vals[3]) : "l"(acc1));
        asm("mov.b64 {%0, %1}, %2;" : "=f"(vals[4]), "=f"(vals[5]) : "l"(acc2));
        asm("mov.b64 {%0, %1}, %2;" : "=f"(vals[6]), "=f"(vals[7]) : "l"(acc3));
        int bprev = batch[n0];
        float run = 0.f;
#pragma unroll
        for (int i = 0; i < 8; i++) {
            float o = vals[i] + b2c;
            o = (o > 0.f) ? o : (__expf(o) - 1.f);  // elu
            int bg = batch[n0 + i];
            if (bg != bprev) {
                atomicAdd(&g_pool[bprev * 512 + c], run);
                run = 0.f;
                bprev = bg;
            }
            run += o;
        }
        atomicAdd(&g_pool[bprev * 512 + c], run);
    }
}

// ============ final: pooled (128KB) in smem, Wo read once per col-slice ======
// grid = 64 blocks x 256 threads; block owns 8 output columns, all 64 graphs.
__global__ void k_final(const float* __restrict__ Wo, const float* __restrict__ bo,
                        float* __restrict__ out) {
    extern __shared__ float sp[];  // 64*512 floats = 128KB
    int t = threadIdx.x;
    for (int idx = t; idx < N_GRAPHS * 512; idx += 256) sp[idx] = g_pool[idx];
    __syncthreads();
    int g0 = t >> 3;                    // 0..31
    int j = t & 7;
    int cc = blockIdx.x * 8 + j;
    float wocol;
    float accA = 0.f, accB = 0.f;
    const float* sA = sp + g0 * 512;
    const float* sB = sp + (g0 + 32) * 512;
#pragma unroll 8
    for (int k = 0; k < 512; k++) {
        wocol = Wo[k * 512 + cc];
        accA += sA[k] * wocol;
        accB += sB[k] * wocol;
    }
    float bb = bo[cc];
    float invA = 1.f / fmaxf((float)g_cnt[g0], 1.f);
    float invB = 1.f / fmaxf((float)g_cnt[g0 + 32], 1.f);
    out[g0 * 512 + cc] = accA * invA + bb;
    out[(g0 + 32) * 512 + cc] = accB * invB + bb;
}

// ---------------- launch -------------------------------------------------------
extern "C" void kernel_launch(void* const* d_in, const int* in_sizes, int n_in,
                              void* d_out, int out_size) {
    const float* x     = (const float*)d_in[0];
    const int*   ei    = (const int*)d_in[1];     // int32 (JAX x64 disabled)
    const int*   batch = (const int*)d_in[2];     // int32
    const float* W1    = (const float*)d_in[3];
    const float* as1   = (const float*)d_in[4];
    const float* ad1   = (const float*)d_in[5];
    const float* b1    = (const float*)d_in[6];
    const float* W2    = (const float*)d_in[7];
    const float* as2   = (const float*)d_in[8];
    const float* ad2   = (const float*)d_in[9];
    const float* b2    = (const float*)d_in[10];
    const float* Wo    = (const float*)d_in[11];
    const float* bo    = (const float*)d_in[12];
    float* out = (float*)d_out;

    static bool attr_done = false;
    if (!attr_done) {
        cudaFuncSetAttribute(k_final, cudaFuncAttributeMaxDynamicSharedMemorySize,
                             N_GRAPHS * 512 * (int)sizeof(float));
        attr_done = true;
    }

    k_setup<<<137, 256>>>(W1, as1, ad1, W2, as2, ad2, batch);
    k_hist<<<(E_TOT + 255) / 256, 256>>>(ei);
    k_scan<<<1, 1024>>>();
    k_scatter_al1<<<1329 + 625, 256>>>(ei, x);
    k_agg1<<<(N_NODES * 8) / 256, 256>>>(x, W1, b1);
    k_agg2<<<N_NODES, 64>>>();
    k_gemm2<<<148, 512>>>(W2, b2, batch);
    k_final<<<N_GRAPHS, 256, N_GRAPHS * 512 * sizeof(float)>>>(Wo, bo, out);
}

// round 4
// speedup vs baseline: 1.1037x; 1.1037x over previous
#include <cuda_runtime.h>

#define N_NODES 20000
#define N_EDGES 320000
#define E_TOT   (N_EDGES + N_NODES)
#define N_GRAPHS 64
#define GEMM_TILE 16
#define GPAD 20

// ---------------- scratch (device globals; no allocation allowed) ----------
__device__ float g_als1[N_NODES * 8];
__device__ float g_ald1[N_NODES * 8];
__device__ float g_o1[N_NODES * 64];
__device__ float g_t2[N_NODES * 64];
__device__ float g_als2[N_NODES];
__device__ float g_ald2[N_NODES];
__device__ float g_va[64];
__device__ float g_vd[64];
__device__ float g_Ps[24];
__device__ float g_Pd[24];
__device__ int   g_deg[N_NODES];
__device__ int   g_fill[N_NODES];        // seeded to rowstart by k_scan
__device__ int   g_rowstart[N_NODES + 1];
__device__ int   g_csr[E_TOT];
__device__ float g_pool[N_GRAPHS * 512];
__device__ int   g_cnt[N_GRAPHS];

// ============ K1: init pool/deg + P + va + per-graph counts (fused) =========
__global__ void k_setup(const float* __restrict__ W1, const float* __restrict__ as1,
                        const float* __restrict__ ad1, const float* __restrict__ W2,
                        const float* __restrict__ as2, const float* __restrict__ ad2,
                        const int* __restrict__ batch) {
    int b = blockIdx.x, t = threadIdx.x;
    if (b < 128) {
        int idx = b * 256 + t;
        g_pool[idx] = 0.f;                       // 128*256 == 32768 exactly
        if (idx < N_NODES) g_deg[idx] = 0;
    } else if (b == 128) {
        if (t < 24) {
            int h = t / 3, d = t % 3;
            float ps = 0.f, pd = 0.f;
            for (int c = 0; c < 8; c++) {
                float w = W1[d * 64 + h * 8 + c];
                ps += w * as1[h * 8 + c];
                pd += w * ad1[h * 8 + c];
            }
            g_Ps[t] = ps;
            g_Pd[t] = pd;
        } else if (t >= 32 && t < 96) {
            int g = t - 32;
            int lo = 0, hi = N_NODES;
            while (lo < hi) { int m = (lo + hi) >> 1; if (batch[m] < g) lo = m + 1; else hi = m; }
            int s = lo;
            lo = 0; hi = N_NODES;
            int g1 = g + 1;
            while (lo < hi) { int m = (lo + hi) >> 1; if (batch[m] < g1) lo = m + 1; else hi = m; }
            g_cnt[g] = lo - s;
        }
    } else {
        int warp = (b - 129) * 8 + (t >> 5);     // 0..63
        int lane = t & 31;
        float s = 0.f, d = 0.f;
        for (int c = lane; c < 512; c += 32) {
            float w = W2[warp * 512 + c];
            s += w * as2[c];
            d += w * ad2[c];
        }
        for (int off = 16; off; off >>= 1) {
            s += __shfl_down_sync(0xffffffffu, s, off);
            d += __shfl_down_sync(0xffffffffu, d, off);
        }
        if (lane == 0) { g_va[warp] = s; g_vd[warp] = d; }
    }
}

// ---------------- CSR build (by dst), incl. self loops -----------------------
__global__ void k_hist(const int* __restrict__ ei) {
    int e = blockIdx.x * blockDim.x + threadIdx.x;
    if (e >= E_TOT) return;
    int dst = (e < N_EDGES) ? ei[N_EDGES + e] : (e - N_EDGES);
    atomicAdd(&g_deg[dst], 1);
}

__global__ void k_scan() {  // 1 block, 1024 threads; also seeds g_fill = rowstart
    __shared__ int part[1024];
    int tid = threadIdx.x;
    const int CH = 20;
    int base = tid * CH;
    int s = 0;
    for (int i = 0; i < CH; i++) {
        int idx = base + i;
        if (idx < N_NODES) s += g_deg[idx];
    }
    part[tid] = s;
    __syncthreads();
    for (int off = 1; off < 1024; off <<= 1) {
        int v = (tid >= off) ? part[tid - off] : 0;
        __syncthreads();
        part[tid] += v;
        __syncthreads();
    }
    int run = (tid == 0) ? 0 : part[tid - 1];
    for (int i = 0; i < CH; i++) {
        int idx = base + i;
        if (idx < N_NODES) {
            g_rowstart[idx] = run;
            g_fill[idx] = run;
            run += g_deg[idx];
        }
    }
    if (tid == 1023) g_rowstart[N_NODES] = part[1023];
}

// ============ scatter (blocks 0..1328) + al1 (blocks 1329..1953) =============
__global__ void k_scatter_al1(const int* __restrict__ ei, const float* __restrict__ x) {
    int b = blockIdx.x, t = threadIdx.x;
    if (b < 1329) {
        int e = b * 256 + t;
        if (e >= E_TOT) return;
        int src, dst;
        if (e < N_EDGES) { src = ei[e]; dst = ei[N_EDGES + e]; }
        else             { src = e - N_EDGES; dst = src; }
        int pos = atomicAdd(&g_fill[dst], 1);
        g_csr[pos] = src;
    } else {
        int idx = (b - 1329) * 256 + t;          // 625*256 == 160000 exactly
        int n = idx >> 3, h = idx & 7;
        float x0 = x[n * 3], x1 = x[n * 3 + 1], x2 = x[n * 3 + 2];
        g_als1[idx] = x0 * g_Ps[h * 3] + x1 * g_Ps[h * 3 + 1] + x2 * g_Ps[h * 3 + 2];
        g_ald1[idx] = x0 * g_Pd[h * 3] + x1 * g_Pd[h * 3 + 1] + x2 * g_Pd[h * 3 + 2];
    }
}

// ---------------- layer-1 aggregate + o1 + fused al2 logits ------------------
__global__ void k_agg1(const float* __restrict__ x, const float* __restrict__ W1,
                       const float* __restrict__ b1) {
    int gidx = blockIdx.x * 256 + threadIdx.x;  // exactly N_NODES*8 threads
    int n = gidx >> 3, h = gidx & 7;
    int s0 = g_rowstart[n], s1 = g_rowstart[n + 1];
    float ald = g_ald1[gidx];
    float wsum = 0.f, xa0 = 0.f, xa1 = 0.f, xa2 = 0.f;
    for (int i = s0; i < s1; i++) {
        int src = g_csr[i];
        float e = g_als1[src * 8 + h] + ald;
        e = (e > 0.f) ? e : 0.2f * e;
        float w = __expf(e);
        wsum += w;
        xa0 += w * x[src * 3 + 0];
        xa1 += w * x[src * 3 + 1];
        xa2 += w * x[src * 3 + 2];
    }
    float inv = 1.f / wsum;
    xa0 *= inv; xa1 *= inv; xa2 *= inv;
    float ps2 = 0.f, pd2 = 0.f;
#pragma unroll
    for (int c = 0; c < 8; c++) {
        int col = h * 8 + c;
        float o = xa0 * W1[col] + xa1 * W1[64 + col] + xa2 * W1[128 + col] + b1[col];
        o = (o > 0.f) ? o : (__expf(o) - 1.f);  // elu
        g_o1[n * 64 + col] = o;
        ps2 += o * g_va[col];
        pd2 += o * g_vd[col];
    }
    for (int off = 4; off; off >>= 1) {
        ps2 += __shfl_down_sync(0xffffffffu, ps2, off);
        pd2 += __shfl_down_sync(0xffffffffu, pd2, off);
    }
    if (h == 0) { g_als2[n] = ps2; g_ald2[n] = pd2; }
}

// ============ layer-2 aggregate v2: shared edge weights, unrolled gather =====
__global__ void k_agg2() {
    __shared__ float sw[64];
    __shared__ int   ssrc[64];
    int n = blockIdx.x;
    int t = threadIdx.x;  // 64
    int s0 = g_rowstart[n], s1 = g_rowstart[n + 1];
    float ald = g_ald2[n];
    float wsum = 0.f, acc = 0.f;
    for (int base = s0; base < s1; base += 64) {
        int i = base + t;
        float w = 0.f;
        int src = 0;
        if (i < s1) {
            src = g_csr[i];
            float e = g_als2[src] + ald;
            e = (e > 0.f) ? e : 0.2f * e;
            w = __expf(e);
        }
        __syncthreads();
        sw[t] = w;
        ssrc[t] = src;
        __syncthreads();
        int m = (s1 - base < 64) ? (s1 - base) : 64;
        int j = 0;
        for (; j + 4 <= m; j += 4) {
            float w0 = sw[j],     w1 = sw[j + 1], w2 = sw[j + 2], w3 = sw[j + 3];
            int   a0 = ssrc[j],   a1 = ssrc[j+1], a2 = ssrc[j+2], a3 = ssrc[j+3];
            float v0 = g_o1[a0 * 64 + t];
            float v1 = g_o1[a1 * 64 + t];
            float v2 = g_o1[a2 * 64 + t];
            float v3 = g_o1[a3 * 64 + t];
            acc += w0 * v0; acc += w1 * v1; acc += w2 * v2; acc += w3 * v3;
            wsum += w0 + w1 + w2 + w3;
        }
        for (; j < m; j++) {
            float wj = sw[j];
            acc += wj * g_o1[ssrc[j] * 64 + t];
            wsum += wj;
        }
    }
    g_t2[n * 64 + t] = acc / wsum;
}

// ============ gemm2 v3: persistent, W2 in regs, 16-node tiles, double buffer =
__global__ void __launch_bounds__(512, 1)
k_gemm2(const float* __restrict__ W2, const float* __restrict__ b2,
        const int* __restrict__ batch) {
    __shared__ __align__(16) float shT[2][64 * GPAD];
    __shared__ int sbat[2][GEMM_TILE];
    int c = threadIdx.x;
    float w[64];
#pragma unroll
    for (int k = 0; k < 64; k++) w[k] = W2[k * 512 + c];
    float b2c = b2[c];
    const int NT = N_NODES / GEMM_TILE;  // 1250
    int kk = c & 63, np = (c >> 6) * 2;  // np in {0,2,...,14}
    int tile = blockIdx.x;               // grid = 148 < NT, every block has work
    // prologue: load first tile into buf 0
    float r0 = g_t2[(tile * GEMM_TILE + np) * 64 + kk];
    float r1 = g_t2[(tile * GEMM_TILE + np + 1) * 64 + kk];
    shT[0][kk * GPAD + np]     = r0;
    shT[0][kk * GPAD + np + 1] = r1;
    if (c < GEMM_TILE) sbat[0][c] = batch[tile * GEMM_TILE + c];
    __syncthreads();
    int buf = 0;
    while (true) {
        int next = tile + (int)gridDim.x;
        bool has_next = (next < NT);
        int nb = 0;
        if (has_next) {
            r0 = g_t2[(next * GEMM_TILE + np) * 64 + kk];
            r1 = g_t2[(next * GEMM_TILE + np + 1) * 64 + kk];
            if (c < GEMM_TILE) nb = batch[next * GEMM_TILE + c];
        }
        unsigned long long acc[8];
#pragma unroll
        for (int i = 0; i < 8; i++) acc[i] = 0ull;
#pragma unroll
        for (int k = 0; k < 64; k++) {
            unsigned long long wp;
            asm("mov.b64 %0, {%1, %1};" : "=l"(wp) : "f"(w[k]));
            const ulonglong2* row = reinterpret_cast<const ulonglong2*>(&shT[buf][k * GPAD]);
            ulonglong2 q0 = row[0];
            ulonglong2 q1 = row[1];
            ulonglong2 q2 = row[2];
            ulonglong2 q3 = row[3];
            asm("fma.rn.f32x2 %0, %1, %2, %0;" : "+l"(acc[0]) : "l"(q0.x), "l"(wp));
            asm("fma.rn.f32x2 %0, %1, %2, %0;" : "+l"(acc[1]) : "l"(q0.y), "l"(wp));
            asm("fma.rn.f32x2 %0, %1, %2, %0;" : "+l"(acc[2]) : "l"(q1.x), "l"(wp));
            asm("fma.rn.f32x2 %0, %1, %2, %0;" : "+l"(acc[3]) : "l"(q1.y), "l"(wp));
            asm("fma.rn.f32x2 %0, %1, %2, %0;" : "+l"(acc[4]) : "l"(q2.x), "l"(wp));
            asm("fma.rn.f32x2 %0, %1, %2, %0;" : "+l"(acc[5]) : "l"(q2.y), "l"(wp));
            asm("fma.rn.f32x2 %0, %1, %2, %0;" : "+l"(acc[6]) : "l"(q3.x), "l"(wp));
            asm("fma.rn.f32x2 %0, %1, %2, %0;" : "+l"(acc[7]) : "l"(q3.y), "l"(wp));
        }
        // epilogue for current tile (reads sbat[buf])
        float vals[16];
#pragma unroll
        for (int i = 0; i < 8; i++)
            asm("mov.b64 {%0, %1}, %2;" : "=f"(vals[2 * i]), "=f"(vals[2 * i + 1]) : "l"(acc[i]));
        int bprev = sbat[buf][0];
        float run = 0.f;
#pragma unroll
        for (int i = 0; i < GEMM_TILE; i++) {
            float o = vals[i] + b2c;
            o = (o > 0.f) ? o : (__expf(o) - 1.f);  // elu
            int bg = sbat[buf][i];
            if (bg != bprev) {
                atomicAdd(&g_pool[bprev * 512 + c], run);
                run = 0.f;
                bprev = bg;
            }
            run += o;
        }
        atomicAdd(&g_pool[bprev * 512 + c], run);
        if (!has_next) break;
        // stage next tile into the other buffer
        int nbuf = buf ^ 1;
        shT[nbuf][kk * GPAD + np]     = r0;
        shT[nbuf][kk * GPAD + np + 1] = r1;
        if (c < GEMM_TILE) sbat[nbuf][c] = nb;
        __syncthreads();
        buf = nbuf;
        tile = next;
    }
}

// ============ final: pooled in smem (one graph per block), Wo streamed =======
__global__ void k_final(const float* __restrict__ Wo, const float* __restrict__ bo,
                        float* __restrict__ out) {
    __shared__ float sp[512];
    int g = blockIdx.x, c = threadIdx.x;
    float cnt = (float)g_cnt[g];
    float inv = 1.f / fmaxf(cnt, 1.f);
    sp[c] = g_pool[g * 512 + c] * inv;
    __syncthreads();
    float acc = bo[c];
#pragma unroll 8
    for (int k = 0; k < 512; k++) acc += sp[k] * Wo[k * 512 + c];
    out[g * 512 + c] = acc;
}

// ---------------- launch -------------------------------------------------------
extern "C" void kernel_launch(void* const* d_in, const int* in_sizes, int n_in,
                              void* d_out, int out_size) {
    const float* x     = (const float*)d_in[0];
    const int*   ei    = (const int*)d_in[1];     // int32 (JAX x64 disabled)
    const int*   batch = (const int*)d_in[2];     // int32
    const float* W1    = (const float*)d_in[3];
    const float* as1   = (const float*)d_in[4];
    const float* ad1   = (const float*)d_in[5];
    const float* b1    = (const float*)d_in[6];
    const float* W2    = (const float*)d_in[7];
    const float* as2   = (const float*)d_in[8];
    const float* ad2   = (const float*)d_in[9];
    const float* b2    = (const float*)d_in[10];
    const float* Wo    = (const float*)d_in[11];
    const float* bo    = (const float*)d_in[12];
    float* out = (float*)d_out;

    k_setup<<<137, 256>>>(W1, as1, ad1, W2, as2, ad2, batch);
    k_hist<<<(E_TOT + 255) / 256, 256>>>(ei);
    k_scan<<<1, 1024>>>();
    k_scatter_al1<<<1329 + 625, 256>>>(ei, x);
    k_agg1<<<(N_NODES * 8) / 256, 256>>>(x, W1, b1);
    k_agg2<<<N_NODES, 64>>>();
    k_gemm2<<<148, 512>>>(W2, b2, batch);
    k_final<<<N_GRAPHS, 512>>>(Wo, bo, out);
}

// round 5
// speedup vs baseline: 1.2724x; 1.1528x over previous
#include <cuda_runtime.h>

#define N_NODES 20000
#define N_EDGES 320000
#define E_TOT   (N_EDGES + N_NODES)
#define N_GRAPHS 64
#define GEMM_TILE 16
#define GPAD 20

// ---------------- scratch (device globals; no allocation allowed) ----------
// INVARIANT: g_deg and g_pool are zero at kernel_launch entry (zero at module
// load; re-zeroed by the tail of each call).
__device__ float g_als1[N_NODES * 8];
__device__ float g_ald1[N_NODES * 8];
__device__ float g_o1[N_NODES * 64];
__device__ float g_t2[N_NODES * 64];
__device__ float g_als2[N_NODES];
__device__ float g_ald2[N_NODES];
__device__ float g_va[64];
__device__ float g_vd[64];
__device__ float g_Ps[24];
__device__ float g_Pd[24];
__device__ int   g_deg[N_NODES];
__device__ int   g_fill[N_NODES];        // seeded to rowstart by the scan
__device__ int   g_rowstart[N_NODES + 1];
__device__ int   g_csr[E_TOT];
__device__ float g_pool[N_GRAPHS * 512];
__device__ int   g_cnt[N_GRAPHS];

// ============ K1: hist + P + va + per-graph counts (fused) ==================
// blocks 0..1328  : degree histogram (g_deg pre-zeroed by invariant)
// block  1329     : t<24 -> P;  t in [32,96) -> cnt via binary search
// blocks 1330..1337: va/vd (64 warps)
__global__ void k_hist_setup(const int* __restrict__ ei,
                             const float* __restrict__ W1, const float* __restrict__ as1,
                             const float* __restrict__ ad1, const float* __restrict__ W2,
                             const float* __restrict__ as2, const float* __restrict__ ad2,
                             const int* __restrict__ batch) {
    int b = blockIdx.x, t = threadIdx.x;
    if (b < 1329) {
        int e = b * 256 + t;
        if (e < E_TOT) {
            int dst = (e < N_EDGES) ? ei[N_EDGES + e] : (e - N_EDGES);
            atomicAdd(&g_deg[dst], 1);
        }
    } else if (b == 1329) {
        if (t < 24) {
            int h = t / 3, d = t % 3;
            float ps = 0.f, pd = 0.f;
            for (int c = 0; c < 8; c++) {
                float w = W1[d * 64 + h * 8 + c];
                ps += w * as1[h * 8 + c];
                pd += w * ad1[h * 8 + c];
            }
            g_Ps[t] = ps;
            g_Pd[t] = pd;
        } else if (t >= 32 && t < 96) {
            int g = t - 32;
            int lo = 0, hi = N_NODES;
            while (lo < hi) { int m = (lo + hi) >> 1; if (batch[m] < g) lo = m + 1; else hi = m; }
            int s = lo;
            lo = 0; hi = N_NODES;
            int g1 = g + 1;
            while (lo < hi) { int m = (lo + hi) >> 1; if (batch[m] < g1) lo = m + 1; else hi = m; }
            g_cnt[g] = lo - s;
        }
    } else {
        int warp = (b - 1330) * 8 + (t >> 5);     // 0..63
        int lane = t & 31;
        float s = 0.f, d = 0.f;
        for (int c = lane; c < 512; c += 32) {
            float w = W2[warp * 512 + c];
            s += w * as2[c];
            d += w * ad2[c];
        }
        for (int off = 16; off; off >>= 1) {
            s += __shfl_down_sync(0xffffffffu, s, off);
            d += __shfl_down_sync(0xffffffffu, d, off);
        }
        if (lane == 0) { g_va[warp] = s; g_vd[warp] = d; }
    }
}

// ============ K2: block 0 = coalesced shuffle-scan; blocks 1..157 = al1 ======
__global__ void __launch_bounds__(1024)
k_scan_al1(const float* __restrict__ x) {
    int b = blockIdx.x, t = threadIdx.x;
    if (b == 0) {
        __shared__ int sw[32];
        int lane = t & 31, w = t >> 5;
        int v[20];
#pragma unroll
        for (int k = 0; k < 20; k++) {
            int i = k * 1024 + t;
            v[k] = (i < N_NODES) ? g_deg[i] : 0;   // 20 independent LDGs, coalesced
        }
        int running = 0;
#pragma unroll
        for (int k = 0; k < 20; k++) {
            int s = v[k];
#pragma unroll
            for (int off = 1; off < 32; off <<= 1) {
                int n = __shfl_up_sync(0xffffffffu, s, off);
                if (lane >= off) s += n;
            }
            if (lane == 31) sw[w] = s;
            __syncthreads();
            if (w == 0) {
                int p = sw[lane];
#pragma unroll
                for (int off = 1; off < 32; off <<= 1) {
                    int n = __shfl_up_sync(0xffffffffu, p, off);
                    if (lane >= off) p += n;
                }
                sw[lane] = p;
            }
            __syncthreads();
            int ex = running + (w ? sw[w - 1] : 0) + s - v[k];  // exclusive prefix
            int i = k * 1024 + t;
            if (i < N_NODES) { g_rowstart[i] = ex; g_fill[i] = ex; }
            running += sw[31];
            __syncthreads();
        }
        if (t == 0) g_rowstart[N_NODES] = running;
    } else {
        int idx = (b - 1) * 1024 + t;
        if (idx < N_NODES * 8) {
            int n = idx >> 3, h = idx & 7;
            float x0 = x[n * 3], x1 = x[n * 3 + 1], x2 = x[n * 3 + 2];
            g_als1[idx] = x0 * g_Ps[h * 3] + x1 * g_Ps[h * 3 + 1] + x2 * g_Ps[h * 3 + 2];
            g_ald1[idx] = x0 * g_Pd[h * 3] + x1 * g_Pd[h * 3 + 1] + x2 * g_Pd[h * 3 + 2];
        }
    }
}

// ============ K3: scatter, 4 edges per thread (MLP=4) ========================
__global__ void k_scatter(const int* __restrict__ ei) {
    int base = blockIdx.x * 1024 + threadIdx.x;
    int src[4], dst[4];
#pragma unroll
    for (int j = 0; j < 4; j++) {
        int e = base + j * 256;
        if (e < E_TOT) {
            if (e < N_EDGES) { src[j] = ei[e]; dst[j] = ei[N_EDGES + e]; }
            else             { src[j] = e - N_EDGES; dst[j] = src[j]; }
        } else dst[j] = -1;
    }
#pragma unroll
    for (int j = 0; j < 4; j++) {
        if (dst[j] >= 0) {
            int pos = atomicAdd(&g_fill[dst[j]], 1);
            g_csr[pos] = src[j];
        }
    }
}

// ---------------- layer-1 aggregate + o1 + fused al2 logits ------------------
__global__ void k_agg1(const float* __restrict__ x, const float* __restrict__ W1,
                       const float* __restrict__ b1) {
    int gidx = blockIdx.x * 256 + threadIdx.x;  // exactly N_NODES*8 threads
    int n = gidx >> 3, h = gidx & 7;
    int s0 = g_rowstart[n], s1 = g_rowstart[n + 1];
    float ald = g_ald1[gidx];
    float wsum = 0.f, xa0 = 0.f, xa1 = 0.f, xa2 = 0.f;
    for (int i = s0; i < s1; i++) {
        int src = g_csr[i];
        float e = g_als1[src * 8 + h] + ald;
        e = (e > 0.f) ? e : 0.2f * e;
        float w = __expf(e);
        wsum += w;
        xa0 += w * x[src * 3 + 0];
        xa1 += w * x[src * 3 + 1];
        xa2 += w * x[src * 3 + 2];
    }
    float inv = 1.f / wsum;
    xa0 *= inv; xa1 *= inv; xa2 *= inv;
    float ps2 = 0.f, pd2 = 0.f;
#pragma unroll
    for (int c = 0; c < 8; c++) {
        int col = h * 8 + c;
        float o = xa0 * W1[col] + xa1 * W1[64 + col] + xa2 * W1[128 + col] + b1[col];
        o = (o > 0.f) ? o : (__expf(o) - 1.f);  // elu
        g_o1[n * 64 + col] = o;
        ps2 += o * g_va[col];
        pd2 += o * g_vd[col];
    }
    for (int off = 4; off; off >>= 1) {
        ps2 += __shfl_down_sync(0xffffffffu, ps2, off);
        pd2 += __shfl_down_sync(0xffffffffu, pd2, off);
    }
    if (h == 0) { g_als2[n] = ps2; g_ald2[n] = pd2; }
}

// ============ layer-2 aggregate: shared edge weights, unrolled gather ========
__global__ void k_agg2() {
    __shared__ float sw[64];
    __shared__ int   ssrc[64];
    int n = blockIdx.x;
    int t = threadIdx.x;  // 64
    int s0 = g_rowstart[n], s1 = g_rowstart[n + 1];
    float ald = g_ald2[n];
    float wsum = 0.f, acc = 0.f;
    for (int base = s0; base < s1; base += 64) {
        int i = base + t;
        float w = 0.f;
        int src = 0;
        if (i < s1) {
            src = g_csr[i];
            float e = g_als2[src] + ald;
            e = (e > 0.f) ? e : 0.2f * e;
            w = __expf(e);
        }
        __syncthreads();
        sw[t] = w;
        ssrc[t] = src;
        __syncthreads();
        int m = (s1 - base < 64) ? (s1 - base) : 64;
        int j = 0;
        for (; j + 4 <= m; j += 4) {
            float w0 = sw[j],     w1 = sw[j + 1], w2 = sw[j + 2], w3 = sw[j + 3];
            int   a0 = ssrc[j],   a1 = ssrc[j+1], a2 = ssrc[j+2], a3 = ssrc[j+3];
            float v0 = g_o1[a0 * 64 + t];
            float v1 = g_o1[a1 * 64 + t];
            float v2 = g_o1[a2 * 64 + t];
            float v3 = g_o1[a3 * 64 + t];
            acc += w0 * v0; acc += w1 * v1; acc += w2 * v2; acc += w3 * v3;
            wsum += w0 + w1 + w2 + w3;
        }
        for (; j < m; j++) {
            float wj = sw[j];
            acc += wj * g_o1[ssrc[j] * 64 + t];
            wsum += wj;
        }
    }
    g_t2[n * 64 + t] = acc / wsum;
}

// ============ gemm2: persistent, W2 in regs, 16-node tiles, double buffer ====
__global__ void __launch_bounds__(512, 1)
k_gemm2(const float* __restrict__ W2, const float* __restrict__ b2,
        const int* __restrict__ batch) {
    __shared__ __align__(16) float shT[2][64 * GPAD];
    __shared__ int sbat[2][GEMM_TILE];
    int c = threadIdx.x;
    float w[64];
#pragma unroll
    for (int k = 0; k < 64; k++) w[k] = W2[k * 512 + c];
    float b2c = b2[c];
    const int NT = N_NODES / GEMM_TILE;  // 1250
    int kk = c & 63, np = (c >> 6) * 2;  // np in {0,2,...,14}
    int tile = blockIdx.x;               // grid = 148 < NT, every block has work
    float r0 = g_t2[(tile * GEMM_TILE + np) * 64 + kk];
    float r1 = g_t2[(tile * GEMM_TILE + np + 1) * 64 + kk];
    shT[0][kk * GPAD + np]     = r0;
    shT[0][kk * GPAD + np + 1] = r1;
    if (c < GEMM_TILE) sbat[0][c] = batch[tile * GEMM_TILE + c];
    __syncthreads();
    int buf = 0;
    while (true) {
        int next = tile + (int)gridDim.x;
        bool has_next = (next < NT);
        int nb = 0;
        if (has_next) {
            r0 = g_t2[(next * GEMM_TILE + np) * 64 + kk];
            r1 = g_t2[(next * GEMM_TILE + np + 1) * 64 + kk];
            if (c < GEMM_TILE) nb = batch[next * GEMM_TILE + c];
        }
        unsigned long long acc[8];
#pragma unroll
        for (int i = 0; i < 8; i++) acc[i] = 0ull;
#pragma unroll
        for (int k = 0; k < 64; k++) {
            unsigned long long wp;
            asm("mov.b64 %0, {%1, %1};" : "=l"(wp) : "f"(w[k]));
            const ulonglong2* row = reinterpret_cast<const ulonglong2*>(&shT[buf][k * GPAD]);
            ulonglong2 q0 = row[0];
            ulonglong2 q1 = row[1];
            ulonglong2 q2 = row[2];
            ulonglong2 q3 = row[3];
            asm("fma.rn.f32x2 %0, %1, %2, %0;" : "+l"(acc[0]) : "l"(q0.x), "l"(wp));
            asm("fma.rn.f32x2 %0, %1, %2, %0;" : "+l"(acc[1]) : "l"(q0.y), "l"(wp));
            asm("fma.rn.f32x2 %0, %1, %2, %0;" : "+l"(acc[2]) : "l"(q1.x), "l"(wp));
            asm("fma.rn.f32x2 %0, %1, %2, %0;" : "+l"(acc[3]) : "l"(q1.y), "l"(wp));
            asm("fma.rn.f32x2 %0, %1, %2, %0;" : "+l"(acc[4]) : "l"(q2.x), "l"(wp));
            asm("fma.rn.f32x2 %0, %1, %2, %0;" : "+l"(acc[5]) : "l"(q2.y), "l"(wp));
            asm("fma.rn.f32x2 %0, %1, %2, %0;" : "+l"(acc[6]) : "l"(q3.x), "l"(wp));
            asm("fma.rn.f32x2 %0, %1, %2, %0;" : "+l"(acc[7]) : "l"(q3.y), "l"(wp));
        }
        float vals[16];
#pragma unroll
        for (int i = 0; i < 8; i++)
            asm("mov.b64 {%0, %1}, %2;" : "=f"(vals[2 * i]), "=f"(vals[2 * i + 1]) : "l"(acc[i]));
        int bprev = sbat[buf][0];
        float run = 0.f;
#pragma unroll
        for (int i = 0; i < GEMM_TILE; i++) {
            float o = vals[i] + b2c;
            o = (o > 0.f) ? o : (__expf(o) - 1.f);  // elu
            int bg = sbat[buf][i];
            if (bg != bprev) {
                atomicAdd(&g_pool[bprev * 512 + c], run);
                run = 0.f;
                bprev = bg;
            }
            run += o;
        }
        atomicAdd(&g_pool[bprev * 512 + c], run);
        if (!has_next) break;
        int nbuf = buf ^ 1;
        shT[nbuf][kk * GPAD + np]     = r0;
        shT[nbuf][kk * GPAD + np + 1] = r1;
        if (c < GEMM_TILE) sbat[nbuf][c] = nb;
        __syncthreads();
        buf = nbuf;
        tile = next;
    }
}

// ============ final (blocks 0..63) + cleanup for next call (blocks 64..103) ==
__global__ void k_final(const float* __restrict__ Wo, const float* __restrict__ bo,
                        float* __restrict__ out) {
    int b = blockIdx.x;
    if (b < 64) {
        __shared__ float sp[512];
        int g = b, c = threadIdx.x;
        float cnt = (float)g_cnt[g];
        float inv = 1.f / fmaxf(cnt, 1.f);
        float p = g_pool[g * 512 + c];
        g_pool[g * 512 + c] = 0.f;           // restore invariant for next call
        sp[c] = p * inv;
        __syncthreads();
        float acc = bo[c];
#pragma unroll 8
        for (int k = 0; k < 512; k++) acc += sp[k] * Wo[k * 512 + c];
        out[g * 512 + c] = acc;
    } else {
        int i = (b - 64) * 512 + threadIdx.x;
        if (i < N_NODES) g_deg[i] = 0;       // restore invariant for next call
    }
}

// ---------------- launch -------------------------------------------------------
extern "C" void kernel_launch(void* const* d_in, const int* in_sizes, int n_in,
                              void* d_out, int out_size) {
    const float* x     = (const float*)d_in[0];
    const int*   ei    = (const int*)d_in[1];     // int32 (JAX x64 disabled)
    const int*   batch = (const int*)d_in[2];     // int32
    const float* W1    = (const float*)d_in[3];
    const float* as1   = (const float*)d_in[4];
    const float* ad1   = (const float*)d_in[5];
    const float* b1    = (const float*)d_in[6];
    const float* W2    = (const float*)d_in[7];
    const float* as2   = (const float*)d_in[8];
    const float* ad2   = (const float*)d_in[9];
    const float* b2    = (const float*)d_in[10];
    const float* Wo    = (const float*)d_in[11];
    const float* bo    = (const float*)d_in[12];
    float* out = (float*)d_out;

    k_hist_setup<<<1338, 256>>>(ei, W1, as1, ad1, W2, as2, ad2, batch);
    k_scan_al1<<<158, 1024>>>(x);
    k_scatter<<<(E_TOT + 1023) / 1024, 256>>>(ei);
    k_agg1<<<(N_NODES * 8) / 256, 256>>>(x, W1, b1);
    k_agg2<<<N_NODES, 64>>>();
    k_gemm2<<<148, 512>>>(W2, b2, batch);
    k_final<<<64 + (N_NODES + 511) / 512, 512>>>(Wo, bo, out);
}

// round 6
// speedup vs baseline: 1.2975x; 1.0197x over previous
#include <cuda_runtime.h>

#define N_NODES 20000
#define N_EDGES 320000
#define E_TOT   (N_EDGES + N_NODES)
#define N_GRAPHS 64
#define GEMM_TILE 16
#define GPAD 20

// ---------------- scratch (device globals; no allocation allowed) ----------
// INVARIANT: g_deg and g_pool are zero at kernel_launch entry (zero at module
// load; re-zeroed by the tail of each call).
__device__ float  g_als1[N_NODES * 8];
__device__ float  g_ald1[N_NODES * 8];
__device__ float4 g_x4[N_NODES];
__device__ float4 g_o14[N_NODES * 16];
__device__ float4 g_t24[N_NODES * 16];
__device__ float  g_als2[N_NODES];
__device__ float  g_ald2[N_NODES];
__device__ float4 g_va4[16];
__device__ float4 g_vd4[16];
__device__ float  g_Ps[24];
__device__ float  g_Pd[24];
__device__ int    g_deg[N_NODES];
__device__ int    g_fill[N_NODES];       // seeded to rowstart by the scan
__device__ int    g_rowstart[N_NODES + 1];
__device__ int    g_csr[E_TOT];
__device__ float  g_pool[N_GRAPHS * 512];
__device__ int    g_cnt[N_GRAPHS];

// ============ K1: hist + P + va + per-graph counts (fused) ==================
__global__ void k_hist_setup(const int* __restrict__ ei,
                             const float* __restrict__ W1, const float* __restrict__ as1,
                             const float* __restrict__ ad1, const float* __restrict__ W2,
                             const float* __restrict__ as2, const float* __restrict__ ad2,
                             const int* __restrict__ batch) {
    int b = blockIdx.x, t = threadIdx.x;
    if (b < 1329) {
        int e = b * 256 + t;
        if (e < E_TOT) {
            int dst = (e < N_EDGES) ? ei[N_EDGES + e] : (e - N_EDGES);
            atomicAdd(&g_deg[dst], 1);
        }
    } else if (b == 1329) {
        if (t < 24) {
            int h = t / 3, d = t % 3;
            float ps = 0.f, pd = 0.f;
            for (int c = 0; c < 8; c++) {
                float w = W1[d * 64 + h * 8 + c];
                ps += w * as1[h * 8 + c];
                pd += w * ad1[h * 8 + c];
            }
            g_Ps[t] = ps;
            g_Pd[t] = pd;
        } else if (t >= 32 && t < 96) {
            int g = t - 32;
            int lo = 0, hi = N_NODES;
            while (lo < hi) { int m = (lo + hi) >> 1; if (batch[m] < g) lo = m + 1; else hi = m; }
            int s = lo;
            lo = 0; hi = N_NODES;
            int g1 = g + 1;
            while (lo < hi) { int m = (lo + hi) >> 1; if (batch[m] < g1) lo = m + 1; else hi = m; }
            g_cnt[g] = lo - s;
        }
    } else {
        int warp = (b - 1330) * 8 + (t >> 5);     // 0..63
        int lane = t & 31;
        float s = 0.f, d = 0.f;
        for (int c = lane; c < 512; c += 32) {
            float w = W2[warp * 512 + c];
            s += w * as2[c];
            d += w * ad2[c];
        }
        for (int off = 16; off; off >>= 1) {
            s += __shfl_down_sync(0xffffffffu, s, off);
            d += __shfl_down_sync(0xffffffffu, d, off);
        }
        if (lane == 0) { ((float*)g_va4)[warp] = s; ((float*)g_vd4)[warp] = d; }
    }
}

// ============ K2: block 0 = coalesced shuffle-scan; blocks 1..157 = al1+x4 ===
__global__ void __launch_bounds__(1024)
k_scan_al1(const float* __restrict__ x) {
    int b = blockIdx.x, t = threadIdx.x;
    if (b == 0) {
        __shared__ int sw[32];
        int lane = t & 31, w = t >> 5;
        int v[20];
#pragma unroll
        for (int k = 0; k < 20; k++) {
            int i = k * 1024 + t;
            v[k] = (i < N_NODES) ? g_deg[i] : 0;
        }
        int running = 0;
#pragma unroll
        for (int k = 0; k < 20; k++) {
            int s = v[k];
#pragma unroll
            for (int off = 1; off < 32; off <<= 1) {
                int n = __shfl_up_sync(0xffffffffu, s, off);
                if (lane >= off) s += n;
            }
            if (lane == 31) sw[w] = s;
            __syncthreads();
            if (w == 0) {
                int p = sw[lane];
#pragma unroll
                for (int off = 1; off < 32; off <<= 1) {
                    int n = __shfl_up_sync(0xffffffffu, p, off);
                    if (lane >= off) p += n;
                }
                sw[lane] = p;
            }
            __syncthreads();
            int ex = running + (w ? sw[w - 1] : 0) + s - v[k];
            int i = k * 1024 + t;
            if (i < N_NODES) { g_rowstart[i] = ex; g_fill[i] = ex; }
            running += sw[31];
            __syncthreads();
        }
        if (t == 0) g_rowstart[N_NODES] = running;
    } else {
        int idx = (b - 1) * 1024 + t;
        if (idx < N_NODES * 8) {
            int n = idx >> 3, h = idx & 7;
            float x0 = x[n * 3], x1 = x[n * 3 + 1], x2 = x[n * 3 + 2];
            g_als1[idx] = x0 * g_Ps[h * 3] + x1 * g_Ps[h * 3 + 1] + x2 * g_Ps[h * 3 + 2];
            g_ald1[idx] = x0 * g_Pd[h * 3] + x1 * g_Pd[h * 3 + 1] + x2 * g_Pd[h * 3 + 2];
            if (h == 0) g_x4[n] = make_float4(x0, x1, x2, 0.f);
        }
    }
}

// ============ K3: scatter, 4 edges per thread (MLP=4) ========================
__global__ void k_scatter(const int* __restrict__ ei) {
    int base = blockIdx.x * 1024 + threadIdx.x;
    int src[4], dst[4];
#pragma unroll
    for (int j = 0; j < 4; j++) {
        int e = base + j * 256;
        if (e < E_TOT) {
            if (e < N_EDGES) { src[j] = ei[e]; dst[j] = ei[N_EDGES + e]; }
            else             { src[j] = e - N_EDGES; dst[j] = src[j]; }
        } else dst[j] = -1;
    }
#pragma unroll
    for (int j = 0; j < 4; j++) {
        if (dst[j] >= 0) {
            int pos = atomicAdd(&g_fill[dst[j]], 1);
            g_csr[pos] = src[j];
        }
    }
}

// ============ layer-1 aggregate v3: 16 lanes/node (8 heads x 2 halves) =======
__global__ void k_agg1(const float* __restrict__ W1, const float* __restrict__ b1) {
    int gidx = blockIdx.x * 256 + threadIdx.x;  // exactly N_NODES*16 threads
    int n = gidx >> 4;
    int l = gidx & 15;          // lane-in-node
    int h = l >> 1, p = l & 1;  // head, half
    int s0 = g_rowstart[n], s1 = g_rowstart[n + 1];
    int half0 = (s1 - s0 + 1) >> 1;
    int a = p ? (s0 + half0) : s0;
    int bnd = p ? s1 : (s0 + half0);
    float ald = g_ald1[n * 8 + h];
    float wsum = 0.f, xa0 = 0.f, xa1 = 0.f, xa2 = 0.f;
    int i = a;
    for (; i + 2 <= bnd; i += 2) {
        int src0 = g_csr[i], src1 = g_csr[i + 1];
        float e0 = g_als1[src0 * 8 + h] + ald;
        float e1 = g_als1[src1 * 8 + h] + ald;
        float4 xv0 = g_x4[src0];
        float4 xv1 = g_x4[src1];
        e0 = (e0 > 0.f) ? e0 : 0.2f * e0;
        e1 = (e1 > 0.f) ? e1 : 0.2f * e1;
        float w0 = __expf(e0), w1 = __expf(e1);
        wsum += w0 + w1;
        xa0 += w0 * xv0.x + w1 * xv1.x;
        xa1 += w0 * xv0.y + w1 * xv1.y;
        xa2 += w0 * xv0.z + w1 * xv1.z;
    }
    if (i < bnd) {
        int src = g_csr[i];
        float e = g_als1[src * 8 + h] + ald;
        float4 xv = g_x4[src];
        e = (e > 0.f) ? e : 0.2f * e;
        float w = __expf(e);
        wsum += w;
        xa0 += w * xv.x; xa1 += w * xv.y; xa2 += w * xv.z;
    }
    // combine the two halves (lane pairs p=0/1)
    wsum += __shfl_xor_sync(0xffffffffu, wsum, 1);
    xa0  += __shfl_xor_sync(0xffffffffu, xa0, 1);
    xa1  += __shfl_xor_sync(0xffffffffu, xa1, 1);
    xa2  += __shfl_xor_sync(0xffffffffu, xa2, 1);
    float inv = 1.f / wsum;
    xa0 *= inv; xa1 *= inv; xa2 *= inv;
    // projection: lane l owns cols 4l..4l+3 (all within head h)
    const float4 w0v = *(const float4*)&W1[4 * l];
    const float4 w1v = *(const float4*)&W1[64 + 4 * l];
    const float4 w2v = *(const float4*)&W1[128 + 4 * l];
    const float4 bv  = *(const float4*)&b1[4 * l];
    float4 o;
    o.x = xa0 * w0v.x + xa1 * w1v.x + xa2 * w2v.x + bv.x;
    o.y = xa0 * w0v.y + xa1 * w1v.y + xa2 * w2v.y + bv.y;
    o.z = xa0 * w0v.z + xa1 * w1v.z + xa2 * w2v.z + bv.z;
    o.w = xa0 * w0v.w + xa1 * w1v.w + xa2 * w2v.w + bv.w;
    o.x = (o.x > 0.f) ? o.x : (__expf(o.x) - 1.f);
    o.y = (o.y > 0.f) ? o.y : (__expf(o.y) - 1.f);
    o.z = (o.z > 0.f) ? o.z : (__expf(o.z) - 1.f);
    o.w = (o.w > 0.f) ? o.w : (__expf(o.w) - 1.f);
    g_o14[n * 16 + l] = o;
    float4 va = g_va4[l], vd = g_vd4[l];
    float ps2 = o.x * va.x + o.y * va.y + o.z * va.z + o.w * va.w;
    float pd2 = o.x * vd.x + o.y * vd.y + o.z * vd.z + o.w * vd.w;
#pragma unroll
    for (int off = 8; off; off >>= 1) {
        ps2 += __shfl_down_sync(0xffffffffu, ps2, off);
        pd2 += __shfl_down_sync(0xffffffffu, pd2, off);
    }
    if (l == 0) { g_als2[n] = ps2; g_ald2[n] = pd2; }
}

// ============ layer-2 aggregate v2: 4-edge x float4-column gather ============
__global__ void k_agg2() {
    __shared__ float sw[64];
    __shared__ int   ssrc[64];
    __shared__ float4 sacc[32];
    __shared__ float swsum[2];
    int n = blockIdx.x;
    int t = threadIdx.x;  // 64
    int q = t & 15, r = t >> 4;
    int s0 = g_rowstart[n], s1 = g_rowstart[n + 1];
    float ald = g_ald2[n];
    float wsum = 0.f;
    float4 acc = make_float4(0.f, 0.f, 0.f, 0.f);
    for (int base = s0; base < s1; base += 64) {
        int i = base + t;
        float w = 0.f;
        int src = 0;
        if (i < s1) {
            src = g_csr[i];
            float e = g_als2[src] + ald;
            e = (e > 0.f) ? e : 0.2f * e;
            w = __expf(e);
        }
        __syncthreads();
        sw[t] = w;
        ssrc[t] = src;
        wsum += w;
        __syncthreads();
        int m = (s1 - base < 64) ? (s1 - base) : 64;
        for (int j = 0; j < m; j += 4) {
            int jr = j + r;
            if (jr < m) {
                float wj = sw[jr];
                float4 v = g_o14[ssrc[jr] * 16 + q];
                acc.x += wj * v.x; acc.y += wj * v.y;
                acc.z += wj * v.z; acc.w += wj * v.w;
            }
        }
    }
    // block-reduce wsum
    float ws = wsum;
#pragma unroll
    for (int off = 16; off; off >>= 1) ws += __shfl_down_sync(0xffffffffu, ws, off);
    if ((t & 31) == 0) swsum[t >> 5] = ws;
    // reduce acc across the 4 edge slots r
    if (t >= 32) sacc[t - 32] = acc;
    __syncthreads();
    if (t < 32) {
        float4 o = sacc[t];
        acc.x += o.x; acc.y += o.y; acc.z += o.z; acc.w += o.w;
        acc.x += __shfl_down_sync(0xffffffffu, acc.x, 16);
        acc.y += __shfl_down_sync(0xffffffffu, acc.y, 16);
        acc.z += __shfl_down_sync(0xffffffffu, acc.z, 16);
        acc.w += __shfl_down_sync(0xffffffffu, acc.w, 16);
        if (t < 16) {
            float inv = 1.f / (swsum[0] + swsum[1]);
            acc.x *= inv; acc.y *= inv; acc.z *= inv; acc.w *= inv;
            g_t24[n * 16 + t] = acc;
        }
    }
}

// ============ gemm2: persistent, W2 in regs, 16-node tiles, double buffer ====
__global__ void __launch_bounds__(512, 1)
k_gemm2(const float* __restrict__ W2, const float* __restrict__ b2,
        const int* __restrict__ batch) {
    __shared__ __align__(16) float shT[2][64 * GPAD];
    __shared__ int sbat[2][GEMM_TILE];
    const float* t2 = (const float*)g_t24;
    int c = threadIdx.x;
    float w[64];
#pragma unroll
    for (int k = 0; k < 64; k++) w[k] = W2[k * 512 + c];
    float b2c = b2[c];
    const int NT = N_NODES / GEMM_TILE;  // 1250
    int kk = c & 63, np = (c >> 6) * 2;
    int tile = blockIdx.x;
    float r0 = t2[(tile * GEMM_TILE + np) * 64 + kk];
    float r1 = t2[(tile * GEMM_TILE + np + 1) * 64 + kk];
    shT[0][kk * GPAD + np]     = r0;
    shT[0][kk * GPAD + np + 1] = r1;
    if (c < GEMM_TILE) sbat[0][c] = batch[tile * GEMM_TILE + c];
    __syncthreads();
    int buf = 0;
    while (true) {
        int next = tile + (int)gridDim.x;
        bool has_next = (next < NT);
        int nb = 0;
        if (has_next) {
            r0 = t2[(next * GEMM_TILE + np) * 64 + kk];
            r1 = t2[(next * GEMM_TILE + np + 1) * 64 + kk];
            if (c < GEMM_TILE) nb = batch[next * GEMM_TILE + c];
        }
        unsigned long long acc[8];
#pragma unroll
        for (int i = 0; i < 8; i++) acc[i] = 0ull;
#pragma unroll
        for (int k = 0; k < 64; k++) {
            unsigned long long wp;
            asm("mov.b64 %0, {%1, %1};" : "=l"(wp) : "f"(w[k]));
            const ulonglong2* row = reinterpret_cast<const ulonglong2*>(&shT[buf][k * GPAD]);
            ulonglong2 q0 = row[0];
            ulonglong2 q1 = row[1];
            ulonglong2 q2 = row[2];
            ulonglong2 q3 = row[3];
            asm("fma.rn.f32x2 %0, %1, %2, %0;" : "+l"(acc[0]) : "l"(q0.x), "l"(wp));
            asm("fma.rn.f32x2 %0, %1, %2, %0;" : "+l"(acc[1]) : "l"(q0.y), "l"(wp));
            asm("fma.rn.f32x2 %0, %1, %2, %0;" : "+l"(acc[2]) : "l"(q1.x), "l"(wp));
            asm("fma.rn.f32x2 %0, %1, %2, %0;" : "+l"(acc[3]) : "l"(q1.y), "l"(wp));
            asm("fma.rn.f32x2 %0, %1, %2, %0;" : "+l"(acc[4]) : "l"(q2.x), "l"(wp));
            asm("fma.rn.f32x2 %0, %1, %2, %0;" : "+l"(acc[5]) : "l"(q2.y), "l"(wp));
            asm("fma.rn.f32x2 %0, %1, %2, %0;" : "+l"(acc[6]) : "l"(q3.x), "l"(wp));
            asm("fma.rn.f32x2 %0, %1, %2, %0;" : "+l"(acc[7]) : "l"(q3.y), "l"(wp));
        }
        float vals[16];
#pragma unroll
        for (int i = 0; i < 8; i++)
            asm("mov.b64 {%0, %1}, %2;" : "=f"(vals[2 * i]), "=f"(vals[2 * i + 1]) : "l"(acc[i]));
        int bprev = sbat[buf][0];
        float run = 0.f;
#pragma unroll
        for (int i = 0; i < GEMM_TILE; i++) {
            float o = vals[i] + b2c;
            o = (o > 0.f) ? o : (__expf(o) - 1.f);  // elu
            int bg = sbat[buf][i];
            if (bg != bprev) {
                atomicAdd(&g_pool[bprev * 512 + c], run);
                run = 0.f;
                bprev = bg;
            }
            run += o;
        }
        atomicAdd(&g_pool[bprev * 512 + c], run);
        if (!has_next) break;
        int nbuf = buf ^ 1;
        shT[nbuf][kk * GPAD + np]     = r0;
        shT[nbuf][kk * GPAD + np + 1] = r1;
        if (c < GEMM_TILE) sbat[nbuf][c] = nb;
        __syncthreads();
        buf = nbuf;
        tile = next;
    }
}

// ============ final (blocks 0..63) + cleanup for next call ===================
__global__ void k_final(const float* __restrict__ Wo, const float* __restrict__ bo,
                        float* __restrict__ out) {
    int b = blockIdx.x;
    if (b < 64) {
        __shared__ float sp[512];
        int g = b, c = threadIdx.x;
        float cnt = (float)g_cnt[g];
        float inv = 1.f / fmaxf(cnt, 1.f);
        float p = g_pool[g * 512 + c];
        g_pool[g * 512 + c] = 0.f;           // restore invariant
        sp[c] = p * inv;
        __syncthreads();
        float acc = bo[c];
#pragma unroll 8
        for (int k = 0; k < 512; k++) acc += sp[k] * Wo[k * 512 + c];
        out[g * 512 + c] = acc;
    } else {
        int i = (b - 64) * 512 + threadIdx.x;
        if (i < N_NODES) g_deg[i] = 0;       // restore invariant
    }
}

// ---------------- launch -------------------------------------------------------
extern "C" void kernel_launch(void* const* d_in, const int* in_sizes, int n_in,
                              void* d_out, int out_size) {
    const float* x     = (const float*)d_in[0];
    const int*   ei    = (const int*)d_in[1];     // int32 (JAX x64 disabled)
    const int*   batch = (const int*)d_in[2];     // int32
    const float* W1    = (const float*)d_in[3];
    const float* as1   = (const float*)d_in[4];
    const float* ad1   = (const float*)d_in[5];
    const float* b1    = (const float*)d_in[6];
    const float* W2    = (const float*)d_in[7];
    const float* as2   = (const float*)d_in[8];
    const float* ad2   = (const float*)d_in[9];
    const float* b2    = (const float*)d_in[10];
    const float* Wo    = (const float*)d_in[11];
    const float* bo    = (const float*)d_in[12];
    float* out = (float*)d_out;

    k_hist_setup<<<1338, 256>>>(ei, W1, as1, ad1, W2, as2, ad2, batch);
    k_scan_al1<<<158, 1024>>>(x);
    k_scatter<<<(E_TOT + 1023) / 1024, 256>>>(ei);
    k_agg1<<<(N_NODES * 16) / 256, 256>>>(W1, b1);
    k_agg2<<<N_NODES, 64>>>();
    k_gemm2<<<148, 512>>>(W2, b2, batch);
    k_final<<<64 + (N_NODES + 511) / 512, 512>>>(Wo, bo, out);
}

// round 7
// speedup vs baseline: 1.3173x; 1.0152x over previous
#include <cuda_runtime.h>

#define N_NODES 20000
#define N_EDGES 320000
#define E_TOT   (N_EDGES + N_NODES)
#define N_GRAPHS 64
#define GEMM_TILE 16
#define GPAD 20
#define SPS 68

// ---------------- scratch (device globals; no allocation allowed) ----------
// INVARIANT: g_deg is zero at kernel_launch entry (zero at module load;
// re-zeroed by the tail of k_final each call). g_pool is zeroed by
// k_hist_setup at the start of each call.
__device__ float  g_als1[N_NODES * 8];
__device__ float  g_ald1[N_NODES * 8];
__device__ float4 g_x4[N_NODES];
__device__ float4 g_o14[N_NODES * 16];
__device__ float4 g_t24[N_NODES * 16];
__device__ float  g_als2[N_NODES];
__device__ float  g_ald2[N_NODES];
__device__ float4 g_va4[16];
__device__ float4 g_vd4[16];
__device__ float  g_Ps[24];
__device__ float  g_Pd[24];
__device__ int    g_deg[N_NODES];
__device__ int    g_fill[N_NODES];       // seeded to rowstart by the scan
__device__ int    g_rowstart[N_NODES + 1];
__device__ int    g_csr[E_TOT];
__device__ float  g_pool[N_GRAPHS * 512];
__device__ int    g_cnt[N_GRAPHS];

// ============ K1: hist + P + va + counts + pool-zero (fused) ================
__global__ void k_hist_setup(const int* __restrict__ ei,
                             const float* __restrict__ W1, const float* __restrict__ as1,
                             const float* __restrict__ ad1, const float* __restrict__ W2,
                             const float* __restrict__ as2, const float* __restrict__ ad2,
                             const int* __restrict__ batch) {
    int b = blockIdx.x, t = threadIdx.x;
    if (b < 1329) {
        int e = b * 256 + t;
        if (e < E_TOT) {
            int dst = (e < N_EDGES) ? ei[N_EDGES + e] : (e - N_EDGES);
            atomicAdd(&g_deg[dst], 1);
        }
    } else if (b == 1329) {
        if (t < 24) {
            int h = t / 3, d = t % 3;
            float ps = 0.f, pd = 0.f;
            for (int c = 0; c < 8; c++) {
                float w = W1[d * 64 + h * 8 + c];
                ps += w * as1[h * 8 + c];
                pd += w * ad1[h * 8 + c];
            }
            g_Ps[t] = ps;
            g_Pd[t] = pd;
        } else if (t >= 32 && t < 96) {
            int g = t - 32;
            int lo = 0, hi = N_NODES;
            while (lo < hi) { int m = (lo + hi) >> 1; if (batch[m] < g) lo = m + 1; else hi = m; }
            int s = lo;
            lo = 0; hi = N_NODES;
            int g1 = g + 1;
            while (lo < hi) { int m = (lo + hi) >> 1; if (batch[m] < g1) lo = m + 1; else hi = m; }
            g_cnt[g] = lo - s;
        }
    } else if (b < 1338) {
        int warp = (b - 1330) * 8 + (t >> 5);     // 0..63
        int lane = t & 31;
        float s = 0.f, d = 0.f;
        for (int c = lane; c < 512; c += 32) {
            float w = W2[warp * 512 + c];
            s += w * as2[c];
            d += w * ad2[c];
        }
        for (int off = 16; off; off >>= 1) {
            s += __shfl_down_sync(0xffffffffu, s, off);
            d += __shfl_down_sync(0xffffffffu, d, off);
        }
        if (lane == 0) { ((float*)g_va4)[warp] = s; ((float*)g_vd4)[warp] = d; }
    } else {
        int idx = (b - 1338) * 256 + t;          // 128*256 == 32768 exactly
        g_pool[idx] = 0.f;
    }
}

// ============ K2: block 0 = coalesced shuffle-scan; blocks 1..157 = al1+x4 ===
__global__ void __launch_bounds__(1024)
k_scan_al1(const float* __restrict__ x) {
    int b = blockIdx.x, t = threadIdx.x;
    if (b == 0) {
        __shared__ int sw[32];
        int lane = t & 31, w = t >> 5;
        int v[20];
#pragma unroll
        for (int k = 0; k < 20; k++) {
            int i = k * 1024 + t;
            v[k] = (i < N_NODES) ? g_deg[i] : 0;
        }
        int running = 0;
#pragma unroll
        for (int k = 0; k < 20; k++) {
            int s = v[k];
#pragma unroll
            for (int off = 1; off < 32; off <<= 1) {
                int n = __shfl_up_sync(0xffffffffu, s, off);
                if (lane >= off) s += n;
            }
            if (lane == 31) sw[w] = s;
            __syncthreads();
            if (w == 0) {
                int p = sw[lane];
#pragma unroll
                for (int off = 1; off < 32; off <<= 1) {
                    int n = __shfl_up_sync(0xffffffffu, p, off);
                    if (lane >= off) p += n;
                }
                sw[lane] = p;
            }
            __syncthreads();
            int ex = running + (w ? sw[w - 1] : 0) + s - v[k];
            int i = k * 1024 + t;
            if (i < N_NODES) { g_rowstart[i] = ex; g_fill[i] = ex; }
            running += sw[31];
            __syncthreads();
        }
        if (t == 0) g_rowstart[N_NODES] = running;
    } else {
        int idx = (b - 1) * 1024 + t;
        if (idx < N_NODES * 8) {
            int n = idx >> 3, h = idx & 7;
            float x0 = x[n * 3], x1 = x[n * 3 + 1], x2 = x[n * 3 + 2];
            g_als1[idx] = x0 * g_Ps[h * 3] + x1 * g_Ps[h * 3 + 1] + x2 * g_Ps[h * 3 + 2];
            g_ald1[idx] = x0 * g_Pd[h * 3] + x1 * g_Pd[h * 3 + 1] + x2 * g_Pd[h * 3 + 2];
            if (h == 0) g_x4[n] = make_float4(x0, x1, x2, 0.f);
        }
    }
}

// ============ K3: scatter, 4 edges per thread (MLP=4) ========================
__global__ void k_scatter(const int* __restrict__ ei) {
    int base = blockIdx.x * 1024 + threadIdx.x;
    int src[4], dst[4];
#pragma unroll
    for (int j = 0; j < 4; j++) {
        int e = base + j * 256;
        if (e < E_TOT) {
            if (e < N_EDGES) { src[j] = ei[e]; dst[j] = ei[N_EDGES + e]; }
            else             { src[j] = e - N_EDGES; dst[j] = src[j]; }
        } else dst[j] = -1;
    }
#pragma unroll
    for (int j = 0; j < 4; j++) {
        if (dst[j] >= 0) {
            int pos = atomicAdd(&g_fill[dst[j]], 1);
            g_csr[pos] = src[j];
        }
    }
}

// ============ layer-1 aggregate v4: thread=(node,quarter), 8 heads in regs ===
__global__ void __launch_bounds__(320)
k_agg1(const float* __restrict__ W1, const float* __restrict__ b1) {
    int gidx = blockIdx.x * 320 + threadIdx.x;   // exactly N_NODES*4 threads
    int n = gidx >> 2, q = gidx & 3;
    int s0 = g_rowstart[n], s1 = g_rowstart[n + 1];
    float4 aldA = *(const float4*)&g_ald1[n * 8];
    float4 aldB = *(const float4*)&g_ald1[n * 8 + 4];
    float wsum[8], xa0[8], xa1[8], xa2[8];
#pragma unroll
    for (int h = 0; h < 8; h++) { wsum[h] = 0.f; xa0[h] = 0.f; xa1[h] = 0.f; xa2[h] = 0.f; }
    for (int i = s0 + q; i < s1; i += 4) {
        int src = g_csr[i];
        float4 asA = *(const float4*)&g_als1[src * 8];
        float4 asB = *(const float4*)&g_als1[src * 8 + 4];
        float4 xv = g_x4[src];
        float e[8] = {asA.x + aldA.x, asA.y + aldA.y, asA.z + aldA.z, asA.w + aldA.w,
                      asB.x + aldB.x, asB.y + aldB.y, asB.z + aldB.z, asB.w + aldB.w};
#pragma unroll
        for (int h = 0; h < 8; h++) {
            float ee = e[h];
            ee = (ee > 0.f) ? ee : 0.2f * ee;
            float w = __expf(ee);
            wsum[h] += w;
            xa0[h] += w * xv.x;
            xa1[h] += w * xv.y;
            xa2[h] += w * xv.z;
        }
    }
    // combine the 4 quarter-lanes (lanes q=0..3 of each node group)
#pragma unroll
    for (int h = 0; h < 8; h++) {
        wsum[h] += __shfl_xor_sync(0xffffffffu, wsum[h], 1);
        wsum[h] += __shfl_xor_sync(0xffffffffu, wsum[h], 2);
        xa0[h]  += __shfl_xor_sync(0xffffffffu, xa0[h], 1);
        xa0[h]  += __shfl_xor_sync(0xffffffffu, xa0[h], 2);
        xa1[h]  += __shfl_xor_sync(0xffffffffu, xa1[h], 1);
        xa1[h]  += __shfl_xor_sync(0xffffffffu, xa1[h], 2);
        xa2[h]  += __shfl_xor_sync(0xffffffffu, xa2[h], 1);
        xa2[h]  += __shfl_xor_sync(0xffffffffu, xa2[h], 2);
        float inv = 1.f / wsum[h];
        xa0[h] *= inv; xa1[h] *= inv; xa2[h] *= inv;
    }
    // projection: lane q owns cols 16q..16q+15 (heads 2q, 2q+1)
    float ps2 = 0.f, pd2 = 0.f;
#pragma unroll
    for (int j = 0; j < 4; j++) {
        int col4 = q * 16 + j * 4;
        int hh = 2 * q + (j >> 1);
        float4 w0 = *(const float4*)&W1[col4];
        float4 w1 = *(const float4*)&W1[64 + col4];
        float4 w2 = *(const float4*)&W1[128 + col4];
        float4 bv = *(const float4*)&b1[col4];
        float4 o;
        o.x = xa0[hh] * w0.x + xa1[hh] * w1.x + xa2[hh] * w2.x + bv.x;
        o.y = xa0[hh] * w0.y + xa1[hh] * w1.y + xa2[hh] * w2.y + bv.y;
        o.z = xa0[hh] * w0.z + xa1[hh] * w1.z + xa2[hh] * w2.z + bv.z;
        o.w = xa0[hh] * w0.w + xa1[hh] * w1.w + xa2[hh] * w2.w + bv.w;
        o.x = (o.x > 0.f) ? o.x : (__expf(o.x) - 1.f);
        o.y = (o.y > 0.f) ? o.y : (__expf(o.y) - 1.f);
        o.z = (o.z > 0.f) ? o.z : (__expf(o.z) - 1.f);
        o.w = (o.w > 0.f) ? o.w : (__expf(o.w) - 1.f);
        g_o14[n * 16 + q * 4 + j] = o;
        float4 va = g_va4[q * 4 + j], vd = g_vd4[q * 4 + j];
        ps2 += o.x * va.x + o.y * va.y + o.z * va.z + o.w * va.w;
        pd2 += o.x * vd.x + o.y * vd.y + o.z * vd.z + o.w * vd.w;
    }
    ps2 += __shfl_xor_sync(0xffffffffu, ps2, 1);
    ps2 += __shfl_xor_sync(0xffffffffu, ps2, 2);
    pd2 += __shfl_xor_sync(0xffffffffu, pd2, 1);
    pd2 += __shfl_xor_sync(0xffffffffu, pd2, 2);
    if (q == 0) { g_als2[n] = ps2; g_ald2[n] = pd2; }
}

// ============ layer-2 aggregate: 4-edge x float4-column gather ===============
__global__ void k_agg2() {
    __shared__ float sw[64];
    __shared__ int   ssrc[64];
    __shared__ float4 sacc[32];
    __shared__ float swsum[2];
    int n = blockIdx.x;
    int t = threadIdx.x;  // 64
    int q = t & 15, r = t >> 4;
    int s0 = g_rowstart[n], s1 = g_rowstart[n + 1];
    float ald = g_ald2[n];
    float wsum = 0.f;
    float4 acc = make_float4(0.f, 0.f, 0.f, 0.f);
    for (int base = s0; base < s1; base += 64) {
        int i = base + t;
        float w = 0.f;
        int src = 0;
        if (i < s1) {
            src = g_csr[i];
            float e = g_als2[src] + ald;
            e = (e > 0.f) ? e : 0.2f * e;
            w = __expf(e);
        }
        __syncthreads();
        sw[t] = w;
        ssrc[t] = src;
        wsum += w;
        __syncthreads();
        int m = (s1 - base < 64) ? (s1 - base) : 64;
        for (int j = 0; j < m; j += 4) {
            int jr = j + r;
            if (jr < m) {
                float wj = sw[jr];
                float4 v = g_o14[ssrc[jr] * 16 + q];
                acc.x += wj * v.x; acc.y += wj * v.y;
                acc.z += wj * v.z; acc.w += wj * v.w;
            }
        }
    }
    float ws = wsum;
#pragma unroll
    for (int off = 16; off; off >>= 1) ws += __shfl_down_sync(0xffffffffu, ws, off);
    if ((t & 31) == 0) swsum[t >> 5] = ws;
    if (t >= 32) sacc[t - 32] = acc;
    __syncthreads();
    if (t < 32) {
        float4 o = sacc[t];
        acc.x += o.x; acc.y += o.y; acc.z += o.z; acc.w += o.w;
        acc.x += __shfl_down_sync(0xffffffffu, acc.x, 16);
        acc.y += __shfl_down_sync(0xffffffffu, acc.y, 16);
        acc.z += __shfl_down_sync(0xffffffffu, acc.z, 16);
        acc.w += __shfl_down_sync(0xffffffffu, acc.w, 16);
        if (t < 16) {
            float inv = 1.f / (swsum[0] + swsum[1]);
            acc.x *= inv; acc.y *= inv; acc.z *= inv; acc.w *= inv;
            g_t24[n * 16 + t] = acc;
        }
    }
}

// ============ gemm2: persistent, W2 in regs, 16-node tiles, double buffer ====
__global__ void __launch_bounds__(512, 1)
k_gemm2(const float* __restrict__ W2, const float* __restrict__ b2,
        const int* __restrict__ batch) {
    __shared__ __align__(16) float shT[2][64 * GPAD];
    __shared__ int sbat[2][GEMM_TILE];
    const float* t2 = (const float*)g_t24;
    int c = threadIdx.x;
    float w[64];
#pragma unroll
    for (int k = 0; k < 64; k++) w[k] = W2[k * 512 + c];
    float b2c = b2[c];
    const int NT = N_NODES / GEMM_TILE;  // 1250
    int kk = c & 63, np = (c >> 6) * 2;
    int tile = blockIdx.x;
    float r0 = t2[(tile * GEMM_TILE + np) * 64 + kk];
    float r1 = t2[(tile * GEMM_TILE + np + 1) * 64 + kk];
    shT[0][kk * GPAD + np]     = r0;
    shT[0][kk * GPAD + np + 1] = r1;
    if (c < GEMM_TILE) sbat[0][c] = batch[tile * GEMM_TILE + c];
    __syncthreads();
    int buf = 0;
    while (true) {
        int next = tile + (int)gridDim.x;
        bool has_next = (next < NT);
        int nb = 0;
        if (has_next) {
            r0 = t2[(next * GEMM_TILE + np) * 64 + kk];
            r1 = t2[(next * GEMM_TILE + np + 1) * 64 + kk];
            if (c < GEMM_TILE) nb = batch[next * GEMM_TILE + c];
        }
        unsigned long long acc[8];
#pragma unroll
        for (int i = 0; i < 8; i++) acc[i] = 0ull;
#pragma unroll
        for (int k = 0; k < 64; k++) {
            unsigned long long wp;
            asm("mov.b64 %0, {%1, %1};" : "=l"(wp) : "f"(w[k]));
            const ulonglong2* row = reinterpret_cast<const ulonglong2*>(&shT[buf][k * GPAD]);
            ulonglong2 q0 = row[0];
            ulonglong2 q1 = row[1];
            ulonglong2 q2 = row[2];
            ulonglong2 q3 = row[3];
            asm("fma.rn.f32x2 %0, %1, %2, %0;" : "+l"(acc[0]) : "l"(q0.x), "l"(wp));
            asm("fma.rn.f32x2 %0, %1, %2, %0;" : "+l"(acc[1]) : "l"(q0.y), "l"(wp));
            asm("fma.rn.f32x2 %0, %1, %2, %0;" : "+l"(acc[2]) : "l"(q1.x), "l"(wp));
            asm("fma.rn.f32x2 %0, %1, %2, %0;" : "+l"(acc[3]) : "l"(q1.y), "l"(wp));
            asm("fma.rn.f32x2 %0, %1, %2, %0;" : "+l"(acc[4]) : "l"(q2.x), "l"(wp));
            asm("fma.rn.f32x2 %0, %1, %2, %0;" : "+l"(acc[5]) : "l"(q2.y), "l"(wp));
            asm("fma.rn.f32x2 %0, %1, %2, %0;" : "+l"(acc[6]) : "l"(q3.x), "l"(wp));
            asm("fma.rn.f32x2 %0, %1, %2, %0;" : "+l"(acc[7]) : "l"(q3.y), "l"(wp));
        }
        float vals[16];
#pragma unroll
        for (int i = 0; i < 8; i++)
            asm("mov.b64 {%0, %1}, %2;" : "=f"(vals[2 * i]), "=f"(vals[2 * i + 1]) : "l"(acc[i]));
        int bprev = sbat[buf][0];
        float run = 0.f;
#pragma unroll
        for (int i = 0; i < GEMM_TILE; i++) {
            float o = vals[i] + b2c;
            o = (o > 0.f) ? o : (__expf(o) - 1.f);  // elu
            int bg = sbat[buf][i];
            if (bg != bprev) {
                atomicAdd(&g_pool[bprev * 512 + c], run);
                run = 0.f;
                bprev = bg;
            }
            run += o;
        }
        atomicAdd(&g_pool[bprev * 512 + c], run);
        if (!has_next) break;
        int nbuf = buf ^ 1;
        shT[nbuf][kk * GPAD + np]     = r0;
        shT[nbuf][kk * GPAD + np + 1] = r1;
        if (c < GEMM_TILE) sbat[nbuf][c] = nb;
        __syncthreads();
        buf = nbuf;
        tile = next;
    }
}

// ============ final v2: block = 8-col slice x all 64 graphs; Wo read once ====
__global__ void k_final(const float* __restrict__ Wo, const float* __restrict__ bo,
                        float* __restrict__ out) {
    int b = blockIdx.x;
    if (b < 64) {
        __shared__ float sP[64 * SPS];   // pooled tile [g][k], padded rows
        __shared__ float sW[64 * 8];     // Wo tile [k][j]
        __shared__ float sInv[64];
        int tid = threadIdx.x;           // 512
        int g = tid >> 3, j = tid & 7;
        int c = b * 8 + j;
        if (tid < 64) sInv[tid] = 1.f / fmaxf((float)g_cnt[tid], 1.f);
        __syncthreads();
        int kk0 = (tid & 7) * 8;         // load role: row g, 8 floats at kk0
        float invg = sInv[g];
        float acc = 0.f;
#pragma unroll 1
        for (int kt = 0; kt < 8; kt++) {
            float4 p0 = *(const float4*)&g_pool[g * 512 + kt * 64 + kk0];
            float4 p1 = *(const float4*)&g_pool[g * 512 + kt * 64 + kk0 + 4];
            p0.x *= invg; p0.y *= invg; p0.z *= invg; p0.w *= invg;
            p1.x *= invg; p1.y *= invg; p1.z *= invg; p1.w *= invg;
            *(float4*)&sP[g * SPS + kk0]     = p0;
            *(float4*)&sP[g * SPS + kk0 + 4] = p1;
            sW[tid] = Wo[(kt * 64 + g) * 512 + c];   // tid == kk*8+j with kk=g
            __syncthreads();
#pragma unroll 8
            for (int kk = 0; kk < 64; kk++)
                acc += sP[g * SPS + kk] * sW[kk * 8 + j];
            __syncthreads();
        }
        out[g * 512 + c] = acc + bo[c];
    } else {
        int i = (b - 64) * 512 + threadIdx.x;
        if (i < N_NODES) g_deg[i] = 0;   // restore invariant for next call
    }
}

// ---------------- launch -------------------------------------------------------
extern "C" void kernel_launch(void* const* d_in, const int* in_sizes, int n_in,
                              void* d_out, int out_size) {
    const float* x     = (const float*)d_in[0];
    const int*   ei    = (const int*)d_in[1];     // int32 (JAX x64 disabled)
    const int*   batch = (const int*)d_in[2];     // int32
    const float* W1    = (const float*)d_in[3];
    const float* as1   = (const float*)d_in[4];
    const float* ad1   = (const float*)d_in[5];
    const float* b1    = (const float*)d_in[6];
    const float* W2    = (const float*)d_in[7];
    const float* as2   = (const float*)d_in[8];
    const float* ad2   = (const float*)d_in[9];
    const float* b2    = (const float*)d_in[10];
    const float* Wo    = (const float*)d_in[11];
    const float* bo    = (const float*)d_in[12];
    float* out = (float*)d_out;

    k_hist_setup<<<1466, 256>>>(ei, W1, as1, ad1, W2, as2, ad2, batch);
    k_scan_al1<<<158, 1024>>>(x);
    k_scatter<<<(E_TOT + 1023) / 1024, 256>>>(ei);
    k_agg1<<<(N_NODES * 4) / 320, 320>>>(W1, b1);
    k_agg2<<<N_NODES, 64>>>();
    k_gemm2<<<148, 512>>>(W2, b2, batch);
    k_final<<<64 + (N_NODES + 511) / 512, 512>>>(Wo, bo, out);
}